// round 14
// baseline (speedup 1.0000x reference)
#include <cuda_runtime.h>
#include <cuda_fp16.h>
#include <cstdint>
#include <math.h>

#define B_ 2
#define T_ 2048
#define C_ 2048
#define H_ 16
#define HKV_ 4
#define D_ 128
#define WINDOW_ 1024
#define SINK_ 4
#define KVC_ (HKV_ * D_)   // 512
#define QKVC_ (C_ + 2 * KVC_)  // 3072
#define SCALE_ 0.08838834764831845f

extern __shared__ char dynsmem[];

__device__ __forceinline__ uint32_t smem_to_u32(const void* p) {
    uint32_t a;
    asm("{ .reg .u64 t; cvta.to.shared.u64 t, %1; cvt.u32.u64 %0, t; }" : "=r"(a) : "l"(p));
    return a;
}

// ---------------------------------------------------------------------------
// Scratch buffers
// ---------------------------------------------------------------------------
__device__ __half g_xh[B_ * T_ * C_];
__device__ __half g_qkv[B_ * T_ * QKVC_];
__device__ __half g_yh[B_ * T_ * C_];
__device__ __half g_wqkv[C_ * QKVC_];        // [K=2048][N=3072]
__device__ __half g_wo[C_ * C_];             // [K=2048][N=2048]
__device__ float2 g_rope[T_ * 64];

// ---------------------------------------------------------------------------
// Fused prep: x conversion + weight conversions + rope table, one launch
// ---------------------------------------------------------------------------
#define NX4 (B_ * T_ * C_ / 4)
#define NQ4 (C_ * C_ / 4)
#define NK4 (C_ * KVC_ / 4)
#define PREP_CONV_TOTAL (NX4 + 2 * NQ4 + 2 * NK4)
#define PREP_TOTAL (PREP_CONV_TOTAL + T_ * 64)

__global__ void prep_kernel(const float* __restrict__ x,
                            const float* __restrict__ Wq,
                            const float* __restrict__ Wk,
                            const float* __restrict__ Wv,
                            const float* __restrict__ Wo,
                            __half* __restrict__ xh,
                            __half* __restrict__ wqkv,
                            __half* __restrict__ wo) {
    int i4 = blockIdx.x * blockDim.x + threadIdx.x;
    if (i4 >= PREP_TOTAL) return;

    if (i4 >= PREP_CONV_TOTAL) {
        int idx = i4 - PREP_CONV_TOTAL;
        int i = idx & 63;
        int t = idx >> 6;
        float inv = powf(10000.0f, -(float)(2 * i) / 128.0f);
        float ang = (float)t * inv;
        float s, c;
        sincosf(ang, &s, &c);
        g_rope[idx] = make_float2(c, s);
        return;
    }

    const float* src;
    __half* dst;
    if (i4 < NX4) {
        int i = i4 * 4;
        src = x + i;
        dst = xh + i;
    } else if (i4 < NX4 + NQ4) {
        int i = (i4 - NX4) * 4;
        int k = i >> 11;
        int c = i & (C_ - 1);
        src = Wq + i;
        dst = wqkv + (size_t)k * QKVC_ + c;
    } else if (i4 < NX4 + NQ4 + NK4) {
        int i = (i4 - NX4 - NQ4) * 4;
        int k = i >> 9;
        int c = i & (KVC_ - 1);
        src = Wk + i;
        dst = wqkv + (size_t)k * QKVC_ + C_ + c;
    } else if (i4 < NX4 + NQ4 + 2 * NK4) {
        int i = (i4 - NX4 - NQ4 - NK4) * 4;
        int k = i >> 9;
        int c = i & (KVC_ - 1);
        src = Wv + i;
        dst = wqkv + (size_t)k * QKVC_ + C_ + KVC_ + c;
    } else {
        int i = (i4 - NX4 - NQ4 - 2 * NK4) * 4;
        src = Wo + i;
        dst = wo + i;
    }
    float4 v = *(const float4*)src;
    *(__half2*)dst       = __floats2half2_rn(v.x, v.y);
    *(__half2*)(dst + 2) = __floats2half2_rn(v.z, v.w);
}

// ---------------------------------------------------------------------------
// RoPE apply (table-driven)
// ---------------------------------------------------------------------------
__global__ void rope_apply_kernel(__half* __restrict__ buf, int total) {
    int idx = blockIdx.x * blockDim.x + threadIdx.x;
    if (idx >= total) return;
    int i = idx & 63;
    int hh = (idx >> 6) % (H_ + HKV_);
    int bt = idx / (64 * (H_ + HKV_));
    int t = bt & (T_ - 1);

    float2 cs = g_rope[t * 64 + i];
    const bool isq = hh < H_;
    const float scale = isq ? SCALE_ : 1.0f;
    const int col = isq ? hh * 128 : C_ + (hh - H_) * 128;

    __half* p = buf + (size_t)bt * QKVC_ + col;
    float x1 = __half2float(p[i]);
    float x2 = __half2float(p[i + 64]);
    p[i]      = __float2half((x1 * cs.x - x2 * cs.y) * scale);
    p[i + 64] = __float2half((x2 * cs.x + x1 * cs.y) * scale);
}

// ---------------------------------------------------------------------------
// MMA helpers
// ---------------------------------------------------------------------------
__device__ __forceinline__ void ldsm_x4(uint32_t* r, uint32_t addr) {
    asm volatile("ldmatrix.sync.aligned.m8n8.x4.shared.b16 {%0,%1,%2,%3}, [%4];"
                 : "=r"(r[0]), "=r"(r[1]), "=r"(r[2]), "=r"(r[3]) : "r"(addr));
}
__device__ __forceinline__ void ldsm_x4_t(uint32_t* r, uint32_t addr) {
    asm volatile("ldmatrix.sync.aligned.m8n8.x4.trans.shared.b16 {%0,%1,%2,%3}, [%4];"
                 : "=r"(r[0]), "=r"(r[1]), "=r"(r[2]), "=r"(r[3]) : "r"(addr));
}
__device__ __forceinline__ void mma16816h(float* d, const uint32_t* a, uint32_t b0, uint32_t b1) {
    asm volatile(
        "mma.sync.aligned.m16n8k16.row.col.f32.f16.f16.f32 "
        "{%0,%1,%2,%3}, {%4,%5,%6,%7}, {%8,%9}, {%0,%1,%2,%3};"
        : "+f"(d[0]), "+f"(d[1]), "+f"(d[2]), "+f"(d[3])
        : "r"(a[0]), "r"(a[1]), "r"(a[2]), "r"(a[3]), "r"(b0), "r"(b1));
}
__device__ __forceinline__ uint32_t packh2(float a, float b) {
    __half2 h = __floats2half2_rn(a, b);
    return *(uint32_t*)&h;
}

// ---------------------------------------------------------------------------
// fp16 GEMM: C[M,N] = A[M,K] @ B[K,N], fp32 accum. B native [K][N] via
// ldmatrix.trans. CTA 128x128, BK=64, 3-stage cp.async, 8 warps (2x4,
// warp tile 64x32), launch_bounds(256,2) -> 2 CTAs/SM (215KB smem total).
// Single sync per chunk: wait -> sync -> prefetch(c+2) -> compute(c).
// ---------------------------------------------------------------------------
#define GROWA 144
#define GROWB 272
#define GTILE_A (128 * GROWA)
#define GTILE_B (64 * GROWB)
#define GSTAGE (GTILE_A + GTILE_B)     // 35840
#define GSMEM_TOTAL (3 * GSTAGE)       // 107520; x2 CTAs = 215040 <= SM carveout

template <bool HALF_OUT>
__global__ __launch_bounds__(256, 2)
void gemm_fp16_kernel(const __half* __restrict__ A,
                      const __half* __restrict__ Bm,
                      void* __restrict__ Cc, int Ndim, int Kdim) {
    uint32_t sb = smem_to_u32(dynsmem);
    const int tid = threadIdx.x;
    const int wid = tid >> 5;
    const int lane = tid & 31;
    const int m0 = blockIdx.y * 128;
    const int n0 = blockIdx.x * 128;
    const int warp_m = (wid >> 2) * 64;
    const int warp_n = (wid & 3) * 32;

    const __half* Abase = A + (size_t)m0 * Kdim;
    const __half* Bbase = Bm + n0;

    auto fill = [&](int stage, int chunk) {
        const int k0 = chunk << 6;
        uint32_t so = sb + stage * GSTAGE;
#pragma unroll
        for (int it = 0; it < 4; it++) {
            int w = tid + it * 256;
            int row = w >> 3, ch = w & 7;
            uint32_t d = so + row * GROWA + ch * 16;
            const void* gA = Abase + (size_t)row * Kdim + k0 + ch * 8;
            asm volatile("cp.async.cg.shared.global [%0], [%1], 16;\n" :: "r"(d), "l"(gA));
        }
#pragma unroll
        for (int it = 0; it < 4; it++) {
            int w = tid + it * 256;
            int row = w >> 4, ch = w & 15;
            uint32_t d = so + GTILE_A + row * GROWB + ch * 16;
            const void* gB = Bbase + (size_t)(k0 + row) * Ndim + ch * 8;
            asm volatile("cp.async.cg.shared.global [%0], [%1], 16;\n" :: "r"(d), "l"(gB));
        }
        asm volatile("cp.async.commit_group;\n" ::: "memory");
    };

    float acc[4][4][4];
#pragma unroll
    for (int i = 0; i < 4; i++)
#pragma unroll
        for (int j = 0; j < 4; j++)
#pragma unroll
            for (int e = 0; e < 4; e++) acc[i][j][e] = 0.0f;

    const int NC = Kdim >> 6;   // >= 2 always here

    fill(0, 0);
    fill(1, 1);

    const int a_row = lane & 15;
    const int a_ch = lane >> 4;
    const int b_row = (lane & 7) + ((lane & 8) ? 8 : 0);
    const int b_cb = (lane & 16) ? 16 : 0;

    for (int c = 0; c < NC; c++) {
        // Pending groups here: {c, c+1}. Drain so that group c is complete.
        if (c + 1 < NC) {
            asm volatile("cp.async.wait_group 1;\n" ::: "memory");
        } else {
            asm volatile("cp.async.wait_group 0;\n" ::: "memory");
        }
        __syncthreads();
        if (c + 2 < NC) fill((c + 2) % 3, c + 2);

        uint32_t sA = sb + (c % 3) * GSTAGE;
        uint32_t sB = sA + GTILE_A;

#pragma unroll
        for (int ks = 0; ks < 4; ks++) {
            uint32_t ah[4][4];
#pragma unroll
            for (int mi = 0; mi < 4; mi++)
                ldsm_x4(ah[mi], sA + (warp_m + mi * 16 + a_row) * GROWA + ks * 32 + a_ch * 16);
            uint32_t bf[4][2];
#pragma unroll
            for (int j = 0; j < 2; j++) {
                uint32_t t4[4];
                ldsm_x4_t(t4, sB + (ks * 16 + b_row) * GROWB + warp_n * 2 + j * 32 + b_cb);
                bf[j * 2][0] = t4[0]; bf[j * 2][1] = t4[1];
                bf[j * 2 + 1][0] = t4[2]; bf[j * 2 + 1][1] = t4[3];
            }
#pragma unroll
            for (int mi = 0; mi < 4; mi++)
#pragma unroll
                for (int ni = 0; ni < 4; ni++)
                    mma16816h(acc[mi][ni], ah[mi], bf[ni][0], bf[ni][1]);
        }
    }

#pragma unroll
    for (int mi = 0; mi < 4; mi++) {
#pragma unroll
        for (int ni = 0; ni < 4; ni++) {
            int r = m0 + warp_m + mi * 16 + (lane >> 2);
            int cc = n0 + warp_n + ni * 8 + 2 * (lane & 3);
            if (HALF_OUT) {
                __half* C = (__half*)Cc;
                *(__half2*)(C + (size_t)r * Ndim + cc) =
                    __floats2half2_rn(acc[mi][ni][0], acc[mi][ni][1]);
                *(__half2*)(C + (size_t)(r + 8) * Ndim + cc) =
                    __floats2half2_rn(acc[mi][ni][2], acc[mi][ni][3]);
            } else {
                float* C = (float*)Cc;
                *(float2*)(C + (size_t)r * Ndim + cc) = make_float2(acc[mi][ni][0], acc[mi][ni][1]);
                *(float2*)(C + (size_t)(r + 8) * Ndim + cc) = make_float2(acc[mi][ni][2], acc[mi][ni][3]);
            }
        }
    }
}

// ---------------------------------------------------------------------------
// HMMA fp16 flash attention: BQ=128, 256 threads / 8 warps (16 q-rows each),
// double-buffered K/V (each tile serves 128 queries), heavy-first order,
// exact per-warp full-mask tile skip (numerically identical to BQ=64).
// ---------------------------------------------------------------------------
#define AROW 136
#define ATILE (64 * AROW)
#define ATILEB (ATILE * 2)             // 17408 per KV tile
#define AQB (128 * 272)                // 34816 Q tile
#define ASMEM_TOTAL (AQB + 4 * ATILEB) // 104448

__global__ __launch_bounds__(256, 1)
void attn_hmma_kernel(const int* __restrict__ seq_lengths) {
    const uint32_t sbase = smem_to_u32(dynsmem);
    const uint32_t qsb = sbase;
    const uint32_t kvb = sbase + AQB;

    const int b = blockIdx.z;
    const int h = blockIdx.y;
    const int q0 = (gridDim.x - 1 - blockIdx.x) * 128;  // heavy-first
    const int hk = h >> 2;
    const int tid = threadIdx.x;
    const int warp = tid >> 5;
    const int lane = tid & 31;
    const int seqlen = seq_lengths[b];
    const int bT = b * T_;
    const int wq0 = q0 + warp * 16;
    const int r0 = lane >> 2;

    const int kthi = (q0 >> 6) + 1;                      // covers q0..q0+127
    const int ktlo = (q0 > WINDOW_) ? ((q0 - WINDOW_) >> 6) : 0;
    const int extra = (ktlo > 0) ? 1 : 0;
    const int nt = (kthi - ktlo + 1) + extra;

    auto kt_of = [&](int it) { return extra ? ((it == 0) ? 0 : (ktlo + it - 1)) : it; };

    auto kv_load = [&](int it, int buf) {
        const int kbase = kt_of(it) * 64;
        const uint32_t kb = kvb + (2 * buf) * ATILEB;
        const uint32_t vb = kvb + (2 * buf + 1) * ATILEB;
#pragma unroll
        for (int i = 0; i < 4; i++) {
            int id = tid + i * 256;
            int row = id >> 4, c = id & 15;
            size_t rbase = (size_t)(bT + kbase + row) * QKVC_ + hk * 128 + c * 8;
            uint32_t soff = row * 272 + c * 16;
            const void* gk = g_qkv + rbase + C_;
            const void* gv = g_qkv + rbase + C_ + KVC_;
            asm volatile("cp.async.cg.shared.global [%0], [%1], 16;\n" :: "r"(kb + soff), "l"(gk));
            asm volatile("cp.async.cg.shared.global [%0], [%1], 16;\n" :: "r"(vb + soff), "l"(gv));
        }
        asm volatile("cp.async.commit_group;\n" ::: "memory");
    };

    // Prologue: Q (128 rows), then KV tile 0
#pragma unroll
    for (int i = 0; i < 8; i++) {
        int id = tid + i * 256;
        int row = id >> 4, c = id & 15;
        const void* g = g_qkv + (size_t)(bT + q0 + row) * QKVC_ + h * 128 + c * 8;
        uint32_t d = qsb + row * 272 + c * 16;
        asm volatile("cp.async.cg.shared.global [%0], [%1], 16;\n" :: "r"(d), "l"(g));
    }
    asm volatile("cp.async.commit_group;\n" ::: "memory");
    kv_load(0, 0);
    asm volatile("cp.async.wait_group 1;\n" ::: "memory");   // Q done
    __syncthreads();

    uint32_t qf[8][4];
    {
        const int lrow = (lane & 7) + ((lane & 8) ? 8 : 0);
        const int lcol = (lane & 16) ? 16 : 0;
#pragma unroll
        for (int ks = 0; ks < 8; ks++)
            ldsm_x4(qf[ks], qsb + (warp * 16 + lrow) * 272 + ks * 32 + lcol);
    }

    float O[16][4];
#pragma unroll
    for (int t = 0; t < 16; t++)
#pragma unroll
        for (int e = 0; e < 4; e++) O[t][e] = 0.0f;
    float m0r = -1e30f, m1r = -1e30f, l0r = 0.0f, l1r = 0.0f;

    const int krowA = (lane & 7) + ((lane & 16) ? 8 : 0);
    const int kcolB = (lane & 8) ? 16 : 0;
    const int vrowA = (lane & 7) + ((lane & 8) ? 8 : 0);
    const int vcolB = (lane & 16) ? 16 : 0;

    for (int it = 0; it < nt; it++) {
        const int buf = it & 1;
        const int kbase = kt_of(it) * 64;

        asm volatile("cp.async.wait_group 0;\n" ::: "memory");
        __syncthreads();
        if (it + 1 < nt) kv_load(it + 1, buf ^ 1);

        // Exact per-warp skip of fully-masked tiles:
        // tile has a valid (q,k) iff it contains a sink key, or
        // [kbase, kbase+63] overlaps [wq0 - WINDOW, wq0 + 15].
        const bool active = (kbase < SINK_) ||
                            ((kbase <= wq0 + 15) && (kbase + 63 >= wq0 - WINDOW_));
        if (active) {
            const uint32_t ksb = kvb + (2 * buf) * ATILEB;
            const uint32_t vsb = kvb + (2 * buf + 1) * ATILEB;

            float S[8][4];
#pragma unroll
            for (int j = 0; j < 8; j++)
#pragma unroll
                for (int e = 0; e < 4; e++) S[j][e] = 0.0f;
#pragma unroll
            for (int ks = 0; ks < 8; ks++) {
#pragma unroll
                for (int np = 0; np < 4; np++) {
                    uint32_t kf[4];
                    ldsm_x4(kf, ksb + (np * 16 + krowA) * 272 + ks * 32 + kcolB);
                    mma16816h(S[2 * np], qf[ks], kf[0], kf[1]);
                    mma16816h(S[2 * np + 1], qf[ks], kf[2], kf[3]);
                }
            }

            const bool needmask = !((kbase + 63 <= wq0) && (wq0 + 15 - kbase <= WINDOW_));
            if (needmask) {
#pragma unroll
                for (int j = 0; j < 8; j++) {
                    int kk = kbase + j * 8 + 2 * (lane & 3);
#pragma unroll
                    for (int e = 0; e < 4; e++) {
                        int q = wq0 + r0 + ((e >= 2) ? 8 : 0);
                        int k = kk + (e & 1);
                        bool ok = (k <= q) && (((q - k) <= WINDOW_) || (k < SINK_));
                        if (!ok) S[j][e] = -1e30f;
                    }
                }
            }

            float mx0 = -1e30f, mx1 = -1e30f;
#pragma unroll
            for (int j = 0; j < 8; j++) {
                mx0 = fmaxf(mx0, fmaxf(S[j][0], S[j][1]));
                mx1 = fmaxf(mx1, fmaxf(S[j][2], S[j][3]));
            }
            mx0 = fmaxf(mx0, __shfl_xor_sync(0xffffffffu, mx0, 1));
            mx0 = fmaxf(mx0, __shfl_xor_sync(0xffffffffu, mx0, 2));
            mx1 = fmaxf(mx1, __shfl_xor_sync(0xffffffffu, mx1, 1));
            mx1 = fmaxf(mx1, __shfl_xor_sync(0xffffffffu, mx1, 2));

            float mn0 = fmaxf(m0r, mx0);
            float mn1 = fmaxf(m1r, mx1);
            float a0 = __expf(m0r - mn0);
            float a1 = __expf(m1r - mn1);
            float s0 = 0.0f, s1 = 0.0f;
#pragma unroll
            for (int j = 0; j < 8; j++) {
                S[j][0] = __expf(S[j][0] - mn0);
                S[j][1] = __expf(S[j][1] - mn0);
                S[j][2] = __expf(S[j][2] - mn1);
                S[j][3] = __expf(S[j][3] - mn1);
                s0 += S[j][0] + S[j][1];
                s1 += S[j][2] + S[j][3];
            }
            s0 += __shfl_xor_sync(0xffffffffu, s0, 1);
            s0 += __shfl_xor_sync(0xffffffffu, s0, 2);
            s1 += __shfl_xor_sync(0xffffffffu, s1, 1);
            s1 += __shfl_xor_sync(0xffffffffu, s1, 2);

            l0r = l0r * a0 + s0;
            l1r = l1r * a1 + s1;
            m0r = mn0;
            m1r = mn1;
#pragma unroll
            for (int t = 0; t < 16; t++) {
                O[t][0] *= a0; O[t][1] *= a0;
                O[t][2] *= a1; O[t][3] *= a1;
            }

#pragma unroll
            for (int ks = 0; ks < 4; ks++) {
                uint32_t pa[4];
                pa[0] = packh2(S[2 * ks][0], S[2 * ks][1]);
                pa[1] = packh2(S[2 * ks][2], S[2 * ks][3]);
                pa[2] = packh2(S[2 * ks + 1][0], S[2 * ks + 1][1]);
                pa[3] = packh2(S[2 * ks + 1][2], S[2 * ks + 1][3]);
#pragma unroll
                for (int nq = 0; nq < 8; nq++) {
                    uint32_t vf[4];
                    ldsm_x4_t(vf, vsb + (ks * 16 + vrowA) * 272 + nq * 32 + vcolB);
                    mma16816h(O[2 * nq], pa, vf[0], vf[1]);
                    mma16816h(O[2 * nq + 1], pa, vf[2], vf[3]);
                }
            }
        }
    }

    const int qr0 = wq0 + r0;
    const int qr1 = qr0 + 8;
    float inv0 = (qr0 < seqlen) ? (1.0f / l0r) : 0.0f;
    float inv1 = (qr1 < seqlen) ? (1.0f / l1r) : 0.0f;
#pragma unroll
    for (int t = 0; t < 16; t++) {
        int col = h * 128 + t * 8 + 2 * (lane & 3);
        *(__half2*)(g_yh + (size_t)(bT + qr0) * C_ + col) =
            __floats2half2_rn(O[t][0] * inv0, O[t][1] * inv0);
        *(__half2*)(g_yh + (size_t)(bT + qr1) * C_ + col) =
            __floats2half2_rn(O[t][2] * inv1, O[t][3] * inv1);
    }
}

// ---------------------------------------------------------------------------
// Launch
// ---------------------------------------------------------------------------
extern "C" void kernel_launch(void* const* d_in, const int* in_sizes, int n_in,
                              void* d_out, int out_size) {
    const float* x  = (const float*)d_in[0];
    const float* Wq = (const float*)d_in[1];
    const float* Wk = (const float*)d_in[2];
    const float* Wv = (const float*)d_in[3];
    const float* Wo = (const float*)d_in[4];
    const int* seq_lengths = (const int*)d_in[5];
    float* out = (float*)d_out;

    __half *xh, *qkv, *yh, *wqkv, *wo;
    cudaGetSymbolAddress((void**)&xh, g_xh);
    cudaGetSymbolAddress((void**)&qkv, g_qkv);
    cudaGetSymbolAddress((void**)&yh, g_yh);
    cudaGetSymbolAddress((void**)&wqkv, g_wqkv);
    cudaGetSymbolAddress((void**)&wo, g_wo);

    const int M = B_ * T_;  // 4096

    cudaFuncSetAttribute((const void*)gemm_fp16_kernel<true>,
                         cudaFuncAttributeMaxDynamicSharedMemorySize, GSMEM_TOTAL);
    cudaFuncSetAttribute((const void*)gemm_fp16_kernel<false>,
                         cudaFuncAttributeMaxDynamicSharedMemorySize, GSMEM_TOTAL);
    cudaFuncSetAttribute((const void*)attn_hmma_kernel,
                         cudaFuncAttributeMaxDynamicSharedMemorySize, ASMEM_TOTAL);

    // Single fused prep launch
    prep_kernel<<<(PREP_TOTAL + 255) / 256, 256>>>(x, Wq, Wk, Wv, Wo, xh, wqkv, wo);

    // Fused QKV projection
    gemm_fp16_kernel<true><<<dim3(QKVC_ / 128, M / 128), 256, GSMEM_TOTAL>>>(
        xh, wqkv, qkv, QKVC_, C_);

    // RoPE apply
    {
        int total = M * (H_ + HKV_) * 64;
        rope_apply_kernel<<<(total + 255) / 256, 256>>>(qkv, total);
    }

    // Attention (BQ=128)
    attn_hmma_kernel<<<dim3(T_ / 128, H_, B_), 256, ASMEM_TOTAL>>>(seq_lengths);

    // Output projection
    gemm_fp16_kernel<false><<<dim3(C_ / 128, M / 128), 256, GSMEM_TOTAL>>>(
        yh, wo, out, C_, C_);
}

// round 15
// speedup vs baseline: 1.0553x; 1.0553x over previous
#include <cuda_runtime.h>
#include <cuda_fp16.h>
#include <cstdint>
#include <math.h>

#define B_ 2
#define T_ 2048
#define C_ 2048
#define H_ 16
#define HKV_ 4
#define D_ 128
#define WINDOW_ 1024
#define SINK_ 4
#define KVC_ (HKV_ * D_)   // 512
#define QKVC_ (C_ + 2 * KVC_)  // 3072
#define SCALE_ 0.08838834764831845f

extern __shared__ char dynsmem[];

__device__ __forceinline__ uint32_t smem_to_u32(const void* p) {
    uint32_t a;
    asm("{ .reg .u64 t; cvta.to.shared.u64 t, %1; cvt.u32.u64 %0, t; }" : "=r"(a) : "l"(p));
    return a;
}

// ---------------------------------------------------------------------------
// Scratch buffers
// ---------------------------------------------------------------------------
__device__ __half g_xh[B_ * T_ * C_];
__device__ __half g_qkv[B_ * T_ * QKVC_];
__device__ __half g_yh[B_ * T_ * C_];
__device__ __half g_wqkv[C_ * QKVC_];        // [K=2048][N=3072]
__device__ __half g_wo[C_ * C_];             // [K=2048][N=2048]
__device__ float2 g_rope[T_ * 64];

// ---------------------------------------------------------------------------
// Fused prep: x conversion + weight conversions + rope table, one launch
// ---------------------------------------------------------------------------
#define NX4 (B_ * T_ * C_ / 4)
#define NQ4 (C_ * C_ / 4)
#define NK4 (C_ * KVC_ / 4)
#define PREP_CONV_TOTAL (NX4 + 2 * NQ4 + 2 * NK4)
#define PREP_TOTAL (PREP_CONV_TOTAL + T_ * 64)

__global__ void prep_kernel(const float* __restrict__ x,
                            const float* __restrict__ Wq,
                            const float* __restrict__ Wk,
                            const float* __restrict__ Wv,
                            const float* __restrict__ Wo,
                            __half* __restrict__ xh,
                            __half* __restrict__ wqkv,
                            __half* __restrict__ wo) {
    int i4 = blockIdx.x * blockDim.x + threadIdx.x;
    if (i4 >= PREP_TOTAL) return;

    if (i4 >= PREP_CONV_TOTAL) {
        int idx = i4 - PREP_CONV_TOTAL;
        int i = idx & 63;
        int t = idx >> 6;
        float inv = powf(10000.0f, -(float)(2 * i) / 128.0f);
        float ang = (float)t * inv;
        float s, c;
        sincosf(ang, &s, &c);
        g_rope[idx] = make_float2(c, s);
        return;
    }

    const float* src;
    __half* dst;
    if (i4 < NX4) {
        int i = i4 * 4;
        src = x + i;
        dst = xh + i;
    } else if (i4 < NX4 + NQ4) {
        int i = (i4 - NX4) * 4;
        int k = i >> 11;
        int c = i & (C_ - 1);
        src = Wq + i;
        dst = wqkv + (size_t)k * QKVC_ + c;
    } else if (i4 < NX4 + NQ4 + NK4) {
        int i = (i4 - NX4 - NQ4) * 4;
        int k = i >> 9;
        int c = i & (KVC_ - 1);
        src = Wk + i;
        dst = wqkv + (size_t)k * QKVC_ + C_ + c;
    } else if (i4 < NX4 + NQ4 + 2 * NK4) {
        int i = (i4 - NX4 - NQ4 - NK4) * 4;
        int k = i >> 9;
        int c = i & (KVC_ - 1);
        src = Wv + i;
        dst = wqkv + (size_t)k * QKVC_ + C_ + KVC_ + c;
    } else {
        int i = (i4 - NX4 - NQ4 - 2 * NK4) * 4;
        src = Wo + i;
        dst = wo + i;
    }
    float4 v = *(const float4*)src;
    *(__half2*)dst       = __floats2half2_rn(v.x, v.y);
    *(__half2*)(dst + 2) = __floats2half2_rn(v.z, v.w);
}

// ---------------------------------------------------------------------------
// RoPE apply (table-driven, 2 rotation indices per thread; identical math)
// Item space: (bt, hh, i2) with i2 in [0,32): handles i = 2*i2 and 2*i2+1.
// ---------------------------------------------------------------------------
__global__ void rope_apply_kernel(__half* __restrict__ buf, int total) {
    int idx = blockIdx.x * blockDim.x + threadIdx.x;
    if (idx >= total) return;
    int i2 = idx & 31;
    int hh = (idx >> 5) % (H_ + HKV_);
    int bt = idx / (32 * (H_ + HKV_));
    int t = bt & (T_ - 1);
    int i = i2 * 2;

    float2 cs0 = g_rope[t * 64 + i];
    float2 cs1 = g_rope[t * 64 + i + 1];
    const bool isq = hh < H_;
    const float scale = isq ? SCALE_ : 1.0f;
    const int col = isq ? hh * 128 : C_ + (hh - H_) * 128;

    __half* p = buf + (size_t)bt * QKVC_ + col;
    __half2 lo = *(__half2*)(p + i);
    __half2 hi = *(__half2*)(p + i + 64);
    float x1a = __half2float(__low2half(lo)),  x1b = __half2float(__high2half(lo));
    float x2a = __half2float(__low2half(hi)),  x2b = __half2float(__high2half(hi));
    *(__half2*)(p + i) = __halves2half2(
        __float2half((x1a * cs0.x - x2a * cs0.y) * scale),
        __float2half((x1b * cs1.x - x2b * cs1.y) * scale));
    *(__half2*)(p + i + 64) = __halves2half2(
        __float2half((x2a * cs0.x + x1a * cs0.y) * scale),
        __float2half((x2b * cs1.x + x1b * cs1.y) * scale));
}

// ---------------------------------------------------------------------------
// MMA helpers
// ---------------------------------------------------------------------------
__device__ __forceinline__ void ldsm_x4(uint32_t* r, uint32_t addr) {
    asm volatile("ldmatrix.sync.aligned.m8n8.x4.shared.b16 {%0,%1,%2,%3}, [%4];"
                 : "=r"(r[0]), "=r"(r[1]), "=r"(r[2]), "=r"(r[3]) : "r"(addr));
}
__device__ __forceinline__ void ldsm_x4_t(uint32_t* r, uint32_t addr) {
    asm volatile("ldmatrix.sync.aligned.m8n8.x4.trans.shared.b16 {%0,%1,%2,%3}, [%4];"
                 : "=r"(r[0]), "=r"(r[1]), "=r"(r[2]), "=r"(r[3]) : "r"(addr));
}
__device__ __forceinline__ void mma16816h(float* d, const uint32_t* a, uint32_t b0, uint32_t b1) {
    asm volatile(
        "mma.sync.aligned.m16n8k16.row.col.f32.f16.f16.f32 "
        "{%0,%1,%2,%3}, {%4,%5,%6,%7}, {%8,%9}, {%0,%1,%2,%3};"
        : "+f"(d[0]), "+f"(d[1]), "+f"(d[2]), "+f"(d[3])
        : "r"(a[0]), "r"(a[1]), "r"(a[2]), "r"(a[3]), "r"(b0), "r"(b1));
}
__device__ __forceinline__ uint32_t packh2(float a, float b) {
    __half2 h = __floats2half2_rn(a, b);
    return *(uint32_t*)&h;
}

// ---------------------------------------------------------------------------
// fp16 GEMM (R13 config): C[M,N] = A[M,K] @ B[K,N], fp32 accum. B native
// [K][N] via ldmatrix.trans. CTA 128x128, BK=64, 2-stage cp.async, 8 warps
// (2x4, warp tile 64x32), launch_bounds(256,2) -> 2 CTAs/SM.
// Single sync per chunk: wait -> sync -> prefetch(c+1) -> compute(c).
// ---------------------------------------------------------------------------
#define GROWA 144
#define GROWB 272
#define GTILE_A (128 * GROWA)
#define GTILE_B (64 * GROWB)
#define GSTAGE (GTILE_A + GTILE_B)     // 35840
#define GSMEM_TOTAL (2 * GSTAGE)       // 71680 -> 2 CTAs/SM

template <bool HALF_OUT>
__global__ __launch_bounds__(256, 2)
void gemm_fp16_kernel(const __half* __restrict__ A,
                      const __half* __restrict__ Bm,
                      void* __restrict__ Cc, int Ndim, int Kdim) {
    uint32_t sb = smem_to_u32(dynsmem);
    const int tid = threadIdx.x;
    const int wid = tid >> 5;
    const int lane = tid & 31;
    const int m0 = blockIdx.y * 128;
    const int n0 = blockIdx.x * 128;
    const int warp_m = (wid >> 2) * 64;
    const int warp_n = (wid & 3) * 32;

    const __half* Abase = A + (size_t)m0 * Kdim;
    const __half* Bbase = Bm + n0;

    auto fill = [&](int stage, int chunk) {
        const int k0 = chunk << 6;
        uint32_t so = sb + stage * GSTAGE;
#pragma unroll
        for (int it = 0; it < 4; it++) {
            int w = tid + it * 256;
            int row = w >> 3, ch = w & 7;
            uint32_t d = so + row * GROWA + ch * 16;
            const void* gA = Abase + (size_t)row * Kdim + k0 + ch * 8;
            asm volatile("cp.async.cg.shared.global [%0], [%1], 16;\n" :: "r"(d), "l"(gA));
        }
#pragma unroll
        for (int it = 0; it < 4; it++) {
            int w = tid + it * 256;
            int row = w >> 4, ch = w & 15;
            uint32_t d = so + GTILE_A + row * GROWB + ch * 16;
            const void* gB = Bbase + (size_t)(k0 + row) * Ndim + ch * 8;
            asm volatile("cp.async.cg.shared.global [%0], [%1], 16;\n" :: "r"(d), "l"(gB));
        }
        asm volatile("cp.async.commit_group;\n" ::: "memory");
    };

    float acc[4][4][4];
#pragma unroll
    for (int i = 0; i < 4; i++)
#pragma unroll
        for (int j = 0; j < 4; j++)
#pragma unroll
            for (int e = 0; e < 4; e++) acc[i][j][e] = 0.0f;

    const int NC = Kdim >> 6;

    fill(0, 0);

    const int a_row = lane & 15;
    const int a_ch = lane >> 4;
    const int b_row = (lane & 7) + ((lane & 8) ? 8 : 0);
    const int b_cb = (lane & 16) ? 16 : 0;

    for (int c = 0; c < NC; c++) {
        asm volatile("cp.async.wait_group 0;\n" ::: "memory");
        __syncthreads();
        if (c + 1 < NC) fill((c + 1) & 1, c + 1);

        uint32_t sA = sb + (c & 1) * GSTAGE;
        uint32_t sB = sA + GTILE_A;

#pragma unroll
        for (int ks = 0; ks < 4; ks++) {
            uint32_t ah[4][4];
#pragma unroll
            for (int mi = 0; mi < 4; mi++)
                ldsm_x4(ah[mi], sA + (warp_m + mi * 16 + a_row) * GROWA + ks * 32 + a_ch * 16);
            uint32_t bf[4][2];
#pragma unroll
            for (int j = 0; j < 2; j++) {
                uint32_t t4[4];
                ldsm_x4_t(t4, sB + (ks * 16 + b_row) * GROWB + warp_n * 2 + j * 32 + b_cb);
                bf[j * 2][0] = t4[0]; bf[j * 2][1] = t4[1];
                bf[j * 2 + 1][0] = t4[2]; bf[j * 2 + 1][1] = t4[3];
            }
#pragma unroll
            for (int mi = 0; mi < 4; mi++)
#pragma unroll
                for (int ni = 0; ni < 4; ni++)
                    mma16816h(acc[mi][ni], ah[mi], bf[ni][0], bf[ni][1]);
        }
    }

#pragma unroll
    for (int mi = 0; mi < 4; mi++) {
#pragma unroll
        for (int ni = 0; ni < 4; ni++) {
            int r = m0 + warp_m + mi * 16 + (lane >> 2);
            int cc = n0 + warp_n + ni * 8 + 2 * (lane & 3);
            if (HALF_OUT) {
                __half* C = (__half*)Cc;
                *(__half2*)(C + (size_t)r * Ndim + cc) =
                    __floats2half2_rn(acc[mi][ni][0], acc[mi][ni][1]);
                *(__half2*)(C + (size_t)(r + 8) * Ndim + cc) =
                    __floats2half2_rn(acc[mi][ni][2], acc[mi][ni][3]);
            } else {
                float* C = (float*)Cc;
                *(float2*)(C + (size_t)r * Ndim + cc) = make_float2(acc[mi][ni][0], acc[mi][ni][1]);
                *(float2*)(C + (size_t)(r + 8) * Ndim + cc) = make_float2(acc[mi][ni][2], acc[mi][ni][3]);
            }
        }
    }
}

// ---------------------------------------------------------------------------
// HMMA fp16 flash attention (R13 config): BQ=64, 128 thr / 4 warps,
// double-buffered K/V, heavy-first, single sync per tile.
// ---------------------------------------------------------------------------
#define AROW 136
#define ATILE (64 * AROW)
#define ATILEB (ATILE * 2)
#define ASMEM_TOTAL (5 * ATILEB)

__global__ __launch_bounds__(128, 2)
void attn_hmma_kernel(const int* __restrict__ seq_lengths) {
    const uint32_t sbase = smem_to_u32(dynsmem);
    const uint32_t qsb = sbase;

    const int b = blockIdx.z;
    const int h = blockIdx.y;
    const int q0 = (gridDim.x - 1 - blockIdx.x) * 64;
    const int hk = h >> 2;
    const int tid = threadIdx.x;
    const int warp = tid >> 5;
    const int lane = tid & 31;
    const int seqlen = seq_lengths[b];
    const int bT = b * T_;
    const int wq0 = q0 + warp * 16;
    const int r0 = lane >> 2;

    const int kthi = q0 >> 6;
    const int ktlo = (q0 > WINDOW_) ? ((q0 - WINDOW_) >> 6) : 0;
    const int extra = (ktlo > 0) ? 1 : 0;
    const int nt = (kthi - ktlo + 1) + extra;

    auto kt_of = [&](int it) { return extra ? ((it == 0) ? 0 : (ktlo + it - 1)) : it; };

    auto kv_load = [&](int it, int buf) {
        const int kbase = kt_of(it) * 64;
        const uint32_t kb = sbase + (1 + 2 * buf) * ATILEB;
        const uint32_t vb = sbase + (2 + 2 * buf) * ATILEB;
#pragma unroll
        for (int i = 0; i < 8; i++) {
            int id = tid + i * 128;
            int row = id >> 4, c = id & 15;
            size_t rbase = (size_t)(bT + kbase + row) * QKVC_ + hk * 128 + c * 8;
            uint32_t soff = row * 272 + c * 16;
            const void* gk = g_qkv + rbase + C_;
            const void* gv = g_qkv + rbase + C_ + KVC_;
            asm volatile("cp.async.cg.shared.global [%0], [%1], 16;\n" :: "r"(kb + soff), "l"(gk));
            asm volatile("cp.async.cg.shared.global [%0], [%1], 16;\n" :: "r"(vb + soff), "l"(gv));
        }
        asm volatile("cp.async.commit_group;\n" ::: "memory");
    };

#pragma unroll
    for (int i = 0; i < 8; i++) {
        int id = tid + i * 128;
        int row = id >> 4, c = id & 15;
        const void* g = g_qkv + (size_t)(bT + q0 + row) * QKVC_ + h * 128 + c * 8;
        uint32_t d = qsb + row * 272 + c * 16;
        asm volatile("cp.async.cg.shared.global [%0], [%1], 16;\n" :: "r"(d), "l"(g));
    }
    asm volatile("cp.async.commit_group;\n" ::: "memory");
    kv_load(0, 0);
    asm volatile("cp.async.wait_group 1;\n" ::: "memory");
    __syncthreads();

    uint32_t qf[8][4];
    {
        const int lrow = (lane & 7) + ((lane & 8) ? 8 : 0);
        const int lcol = (lane & 16) ? 16 : 0;
#pragma unroll
        for (int ks = 0; ks < 8; ks++)
            ldsm_x4(qf[ks], qsb + (warp * 16 + lrow) * 272 + ks * 32 + lcol);
    }

    float O[16][4];
#pragma unroll
    for (int t = 0; t < 16; t++)
#pragma unroll
        for (int e = 0; e < 4; e++) O[t][e] = 0.0f;
    float m0r = -1e30f, m1r = -1e30f, l0r = 0.0f, l1r = 0.0f;

    const int krowA = (lane & 7) + ((lane & 16) ? 8 : 0);
    const int kcolB = (lane & 8) ? 16 : 0;
    const int vrowA = (lane & 7) + ((lane & 8) ? 8 : 0);
    const int vcolB = (lane & 16) ? 16 : 0;

    for (int it = 0; it < nt; it++) {
        const int buf = it & 1;
        const int kbase = kt_of(it) * 64;

        asm volatile("cp.async.wait_group 0;\n" ::: "memory");
        __syncthreads();
        if (it + 1 < nt) kv_load(it + 1, buf ^ 1);

        const uint32_t ksb = sbase + (1 + 2 * buf) * ATILEB;
        const uint32_t vsb = sbase + (2 + 2 * buf) * ATILEB;

        float S[8][4];
#pragma unroll
        for (int j = 0; j < 8; j++)
#pragma unroll
            for (int e = 0; e < 4; e++) S[j][e] = 0.0f;
#pragma unroll
        for (int ks = 0; ks < 8; ks++) {
#pragma unroll
            for (int np = 0; np < 4; np++) {
                uint32_t kf[4];
                ldsm_x4(kf, ksb + (np * 16 + krowA) * 272 + ks * 32 + kcolB);
                mma16816h(S[2 * np], qf[ks], kf[0], kf[1]);
                mma16816h(S[2 * np + 1], qf[ks], kf[2], kf[3]);
            }
        }

        const bool needmask = !((kbase + 63 <= wq0) && (wq0 + 15 - kbase <= WINDOW_));
        if (needmask) {
#pragma unroll
            for (int j = 0; j < 8; j++) {
                int kk = kbase + j * 8 + 2 * (lane & 3);
#pragma unroll
                for (int e = 0; e < 4; e++) {
                    int q = wq0 + r0 + ((e >= 2) ? 8 : 0);
                    int k = kk + (e & 1);
                    bool ok = (k <= q) && (((q - k) <= WINDOW_) || (k < SINK_));
                    if (!ok) S[j][e] = -1e30f;
                }
            }
        }

        float mx0 = -1e30f, mx1 = -1e30f;
#pragma unroll
        for (int j = 0; j < 8; j++) {
            mx0 = fmaxf(mx0, fmaxf(S[j][0], S[j][1]));
            mx1 = fmaxf(mx1, fmaxf(S[j][2], S[j][3]));
        }
        mx0 = fmaxf(mx0, __shfl_xor_sync(0xffffffffu, mx0, 1));
        mx0 = fmaxf(mx0, __shfl_xor_sync(0xffffffffu, mx0, 2));
        mx1 = fmaxf(mx1, __shfl_xor_sync(0xffffffffu, mx1, 1));
        mx1 = fmaxf(mx1, __shfl_xor_sync(0xffffffffu, mx1, 2));

        float mn0 = fmaxf(m0r, mx0);
        float mn1 = fmaxf(m1r, mx1);
        float a0 = __expf(m0r - mn0);
        float a1 = __expf(m1r - mn1);
        float s0 = 0.0f, s1 = 0.0f;
#pragma unroll
        for (int j = 0; j < 8; j++) {
            S[j][0] = __expf(S[j][0] - mn0);
            S[j][1] = __expf(S[j][1] - mn0);
            S[j][2] = __expf(S[j][2] - mn1);
            S[j][3] = __expf(S[j][3] - mn1);
            s0 += S[j][0] + S[j][1];
            s1 += S[j][2] + S[j][3];
        }
        s0 += __shfl_xor_sync(0xffffffffu, s0, 1);
        s0 += __shfl_xor_sync(0xffffffffu, s0, 2);
        s1 += __shfl_xor_sync(0xffffffffu, s1, 1);
        s1 += __shfl_xor_sync(0xffffffffu, s1, 2);

        l0r = l0r * a0 + s0;
        l1r = l1r * a1 + s1;
        m0r = mn0;
        m1r = mn1;
#pragma unroll
        for (int t = 0; t < 16; t++) {
            O[t][0] *= a0; O[t][1] *= a0;
            O[t][2] *= a1; O[t][3] *= a1;
        }

#pragma unroll
        for (int ks = 0; ks < 4; ks++) {
            uint32_t pa[4];
            pa[0] = packh2(S[2 * ks][0], S[2 * ks][1]);
            pa[1] = packh2(S[2 * ks][2], S[2 * ks][3]);
            pa[2] = packh2(S[2 * ks + 1][0], S[2 * ks + 1][1]);
            pa[3] = packh2(S[2 * ks + 1][2], S[2 * ks + 1][3]);
#pragma unroll
            for (int nq = 0; nq < 8; nq++) {
                uint32_t vf[4];
                ldsm_x4_t(vf, vsb + (ks * 16 + vrowA) * 272 + nq * 32 + vcolB);
                mma16816h(O[2 * nq], pa, vf[0], vf[1]);
                mma16816h(O[2 * nq + 1], pa, vf[2], vf[3]);
            }
        }
    }

    const int qr0 = wq0 + r0;
    const int qr1 = qr0 + 8;
    float inv0 = (qr0 < seqlen) ? (1.0f / l0r) : 0.0f;
    float inv1 = (qr1 < seqlen) ? (1.0f / l1r) : 0.0f;
#pragma unroll
    for (int t = 0; t < 16; t++) {
        int col = h * 128 + t * 8 + 2 * (lane & 3);
        *(__half2*)(g_yh + (size_t)(bT + qr0) * C_ + col) =
            __floats2half2_rn(O[t][0] * inv0, O[t][1] * inv0);
        *(__half2*)(g_yh + (size_t)(bT + qr1) * C_ + col) =
            __floats2half2_rn(O[t][2] * inv1, O[t][3] * inv1);
    }
}

// ---------------------------------------------------------------------------
// Launch
// ---------------------------------------------------------------------------
extern "C" void kernel_launch(void* const* d_in, const int* in_sizes, int n_in,
                              void* d_out, int out_size) {
    const float* x  = (const float*)d_in[0];
    const float* Wq = (const float*)d_in[1];
    const float* Wk = (const float*)d_in[2];
    const float* Wv = (const float*)d_in[3];
    const float* Wo = (const float*)d_in[4];
    const int* seq_lengths = (const int*)d_in[5];
    float* out = (float*)d_out;

    __half *xh, *qkv, *yh, *wqkv, *wo;
    cudaGetSymbolAddress((void**)&xh, g_xh);
    cudaGetSymbolAddress((void**)&qkv, g_qkv);
    cudaGetSymbolAddress((void**)&yh, g_yh);
    cudaGetSymbolAddress((void**)&wqkv, g_wqkv);
    cudaGetSymbolAddress((void**)&wo, g_wo);

    const int M = B_ * T_;  // 4096

    cudaFuncSetAttribute((const void*)gemm_fp16_kernel<true>,
                         cudaFuncAttributeMaxDynamicSharedMemorySize, GSMEM_TOTAL);
    cudaFuncSetAttribute((const void*)gemm_fp16_kernel<false>,
                         cudaFuncAttributeMaxDynamicSharedMemorySize, GSMEM_TOTAL);
    cudaFuncSetAttribute((const void*)attn_hmma_kernel,
                         cudaFuncAttributeMaxDynamicSharedMemorySize, ASMEM_TOTAL);

    // Single fused prep launch
    prep_kernel<<<(PREP_TOTAL + 255) / 256, 256>>>(x, Wq, Wk, Wv, Wo, xh, wqkv, wo);

    // Fused QKV projection
    gemm_fp16_kernel<true><<<dim3(QKVC_ / 128, M / 128), 256, GSMEM_TOTAL>>>(
        xh, wqkv, qkv, QKVC_, C_);

    // RoPE apply (2 indices per thread)
    {
        int total = M * (H_ + HKV_) * 32;
        rope_apply_kernel<<<(total + 255) / 256, 256>>>(qkv, total);
    }

    // Attention (BQ=64, heavy-first)
    attn_hmma_kernel<<<dim3(T_ / 64, H_, B_), 128, ASMEM_TOTAL>>>(seq_lengths);

    // Output projection
    gemm_fp16_kernel<false><<<dim3(C_ / 128, M / 128), 256, GSMEM_TOTAL>>>(
        yh, wo, out, C_, C_);
}

// round 16
// speedup vs baseline: 1.0591x; 1.0035x over previous
#include <cuda_runtime.h>
#include <cuda_fp16.h>
#include <cstdint>
#include <math.h>

#define B_ 2
#define T_ 2048
#define C_ 2048
#define H_ 16
#define HKV_ 4
#define D_ 128
#define WINDOW_ 1024
#define SINK_ 4
#define KVC_ (HKV_ * D_)   // 512
#define QKVC_ (C_ + 2 * KVC_)  // 3072
#define SCALE_ 0.08838834764831845f

extern __shared__ char dynsmem[];

__device__ __forceinline__ uint32_t smem_to_u32(const void* p) {
    uint32_t a;
    asm("{ .reg .u64 t; cvta.to.shared.u64 t, %1; cvt.u32.u64 %0, t; }" : "=r"(a) : "l"(p));
    return a;
}

// ---------------------------------------------------------------------------
// Scratch buffers
// ---------------------------------------------------------------------------
__device__ __half g_xh[B_ * T_ * C_];
__device__ __half g_qkv[B_ * T_ * QKVC_];
__device__ __half g_yh[B_ * T_ * C_];
__device__ __half g_wqkv[C_ * QKVC_];        // [K=2048][N=3072]
__device__ __half g_wo[C_ * C_];             // [K=2048][N=2048]
__device__ float2 g_rope[T_ * 64];

// ---------------------------------------------------------------------------
// Fused prep: x conversion + weight conversions + rope table, one launch
// ---------------------------------------------------------------------------
#define NX4 (B_ * T_ * C_ / 4)
#define NQ4 (C_ * C_ / 4)
#define NK4 (C_ * KVC_ / 4)
#define PREP_CONV_TOTAL (NX4 + 2 * NQ4 + 2 * NK4)
#define PREP_TOTAL (PREP_CONV_TOTAL + T_ * 64)

__global__ void prep_kernel(const float* __restrict__ x,
                            const float* __restrict__ Wq,
                            const float* __restrict__ Wk,
                            const float* __restrict__ Wv,
                            const float* __restrict__ Wo,
                            __half* __restrict__ xh,
                            __half* __restrict__ wqkv,
                            __half* __restrict__ wo) {
    int i4 = blockIdx.x * blockDim.x + threadIdx.x;
    if (i4 >= PREP_TOTAL) return;

    if (i4 >= PREP_CONV_TOTAL) {
        int idx = i4 - PREP_CONV_TOTAL;
        int i = idx & 63;
        int t = idx >> 6;
        float inv = powf(10000.0f, -(float)(2 * i) / 128.0f);
        float ang = (float)t * inv;
        float s, c;
        sincosf(ang, &s, &c);
        g_rope[idx] = make_float2(c, s);
        return;
    }

    const float* src;
    __half* dst;
    if (i4 < NX4) {
        int i = i4 * 4;
        src = x + i;
        dst = xh + i;
    } else if (i4 < NX4 + NQ4) {
        int i = (i4 - NX4) * 4;
        int k = i >> 11;
        int c = i & (C_ - 1);
        src = Wq + i;
        dst = wqkv + (size_t)k * QKVC_ + c;
    } else if (i4 < NX4 + NQ4 + NK4) {
        int i = (i4 - NX4 - NQ4) * 4;
        int k = i >> 9;
        int c = i & (KVC_ - 1);
        src = Wk + i;
        dst = wqkv + (size_t)k * QKVC_ + C_ + c;
    } else if (i4 < NX4 + NQ4 + 2 * NK4) {
        int i = (i4 - NX4 - NQ4 - NK4) * 4;
        int k = i >> 9;
        int c = i & (KVC_ - 1);
        src = Wv + i;
        dst = wqkv + (size_t)k * QKVC_ + C_ + KVC_ + c;
    } else {
        int i = (i4 - NX4 - NQ4 - 2 * NK4) * 4;
        src = Wo + i;
        dst = wo + i;
    }
    float4 v = *(const float4*)src;
    *(__half2*)dst       = __floats2half2_rn(v.x, v.y);
    *(__half2*)(dst + 2) = __floats2half2_rn(v.z, v.w);
}

// ---------------------------------------------------------------------------
// RoPE apply (table-driven, 2 rotation indices per thread)
// ---------------------------------------------------------------------------
__global__ void rope_apply_kernel(__half* __restrict__ buf, int total) {
    int idx = blockIdx.x * blockDim.x + threadIdx.x;
    if (idx >= total) return;
    int i2 = idx & 31;
    int hh = (idx >> 5) % (H_ + HKV_);
    int bt = idx / (32 * (H_ + HKV_));
    int t = bt & (T_ - 1);
    int i = i2 * 2;

    float2 cs0 = g_rope[t * 64 + i];
    float2 cs1 = g_rope[t * 64 + i + 1];
    const bool isq = hh < H_;
    const float scale = isq ? SCALE_ : 1.0f;
    const int col = isq ? hh * 128 : C_ + (hh - H_) * 128;

    __half* p = buf + (size_t)bt * QKVC_ + col;
    __half2 lo = *(__half2*)(p + i);
    __half2 hi = *(__half2*)(p + i + 64);
    float x1a = __half2float(__low2half(lo)),  x1b = __half2float(__high2half(lo));
    float x2a = __half2float(__low2half(hi)),  x2b = __half2float(__high2half(hi));
    *(__half2*)(p + i) = __halves2half2(
        __float2half((x1a * cs0.x - x2a * cs0.y) * scale),
        __float2half((x1b * cs1.x - x2b * cs1.y) * scale));
    *(__half2*)(p + i + 64) = __halves2half2(
        __float2half((x2a * cs0.x + x1a * cs0.y) * scale),
        __float2half((x2b * cs1.x + x1b * cs1.y) * scale));
}

// ---------------------------------------------------------------------------
// MMA helpers
// ---------------------------------------------------------------------------
__device__ __forceinline__ void ldsm_x4(uint32_t* r, uint32_t addr) {
    asm volatile("ldmatrix.sync.aligned.m8n8.x4.shared.b16 {%0,%1,%2,%3}, [%4];"
                 : "=r"(r[0]), "=r"(r[1]), "=r"(r[2]), "=r"(r[3]) : "r"(addr));
}
__device__ __forceinline__ void ldsm_x4_t(uint32_t* r, uint32_t addr) {
    asm volatile("ldmatrix.sync.aligned.m8n8.x4.trans.shared.b16 {%0,%1,%2,%3}, [%4];"
                 : "=r"(r[0]), "=r"(r[1]), "=r"(r[2]), "=r"(r[3]) : "r"(addr));
}
__device__ __forceinline__ void mma16816h(float* d, const uint32_t* a, uint32_t b0, uint32_t b1) {
    asm volatile(
        "mma.sync.aligned.m16n8k16.row.col.f32.f16.f16.f32 "
        "{%0,%1,%2,%3}, {%4,%5,%6,%7}, {%8,%9}, {%0,%1,%2,%3};"
        : "+f"(d[0]), "+f"(d[1]), "+f"(d[2]), "+f"(d[3])
        : "r"(a[0]), "r"(a[1]), "r"(a[2]), "r"(a[3]), "r"(b0), "r"(b1));
}
__device__ __forceinline__ uint32_t packh2(float a, float b) {
    __half2 h = __floats2half2_rn(a, b);
    return *(uint32_t*)&h;
}

// ---------------------------------------------------------------------------
// fp16 GEMM (R13/R15 config): CTA 128x128, BK=64, 2-stage cp.async, 8 warps
// (2x4, warp tile 64x32), launch_bounds(256,2) -> 2 CTAs/SM.
// ---------------------------------------------------------------------------
#define GROWA 144
#define GROWB 272
#define GTILE_A (128 * GROWA)
#define GTILE_B (64 * GROWB)
#define GSTAGE (GTILE_A + GTILE_B)     // 35840
#define GSMEM_TOTAL (2 * GSTAGE)       // 71680

template <bool HALF_OUT>
__global__ __launch_bounds__(256, 2)
void gemm_fp16_kernel(const __half* __restrict__ A,
                      const __half* __restrict__ Bm,
                      void* __restrict__ Cc, int Ndim, int Kdim) {
    uint32_t sb = smem_to_u32(dynsmem);
    const int tid = threadIdx.x;
    const int wid = tid >> 5;
    const int lane = tid & 31;
    const int m0 = blockIdx.y * 128;
    const int n0 = blockIdx.x * 128;
    const int warp_m = (wid >> 2) * 64;
    const int warp_n = (wid & 3) * 32;

    const __half* Abase = A + (size_t)m0 * Kdim;
    const __half* Bbase = Bm + n0;

    auto fill = [&](int stage, int chunk) {
        const int k0 = chunk << 6;
        uint32_t so = sb + stage * GSTAGE;
#pragma unroll
        for (int it = 0; it < 4; it++) {
            int w = tid + it * 256;
            int row = w >> 3, ch = w & 7;
            uint32_t d = so + row * GROWA + ch * 16;
            const void* gA = Abase + (size_t)row * Kdim + k0 + ch * 8;
            asm volatile("cp.async.cg.shared.global [%0], [%1], 16;\n" :: "r"(d), "l"(gA));
        }
#pragma unroll
        for (int it = 0; it < 4; it++) {
            int w = tid + it * 256;
            int row = w >> 4, ch = w & 15;
            uint32_t d = so + GTILE_A + row * GROWB + ch * 16;
            const void* gB = Bbase + (size_t)(k0 + row) * Ndim + ch * 8;
            asm volatile("cp.async.cg.shared.global [%0], [%1], 16;\n" :: "r"(d), "l"(gB));
        }
        asm volatile("cp.async.commit_group;\n" ::: "memory");
    };

    float acc[4][4][4];
#pragma unroll
    for (int i = 0; i < 4; i++)
#pragma unroll
        for (int j = 0; j < 4; j++)
#pragma unroll
            for (int e = 0; e < 4; e++) acc[i][j][e] = 0.0f;

    const int NC = Kdim >> 6;

    fill(0, 0);

    const int a_row = lane & 15;
    const int a_ch = lane >> 4;
    const int b_row = (lane & 7) + ((lane & 8) ? 8 : 0);
    const int b_cb = (lane & 16) ? 16 : 0;

    for (int c = 0; c < NC; c++) {
        asm volatile("cp.async.wait_group 0;\n" ::: "memory");
        __syncthreads();
        if (c + 1 < NC) fill((c + 1) & 1, c + 1);

        uint32_t sA = sb + (c & 1) * GSTAGE;
        uint32_t sB = sA + GTILE_A;

#pragma unroll
        for (int ks = 0; ks < 4; ks++) {
            uint32_t ah[4][4];
#pragma unroll
            for (int mi = 0; mi < 4; mi++)
                ldsm_x4(ah[mi], sA + (warp_m + mi * 16 + a_row) * GROWA + ks * 32 + a_ch * 16);
            uint32_t bf[4][2];
#pragma unroll
            for (int j = 0; j < 2; j++) {
                uint32_t t4[4];
                ldsm_x4_t(t4, sB + (ks * 16 + b_row) * GROWB + warp_n * 2 + j * 32 + b_cb);
                bf[j * 2][0] = t4[0]; bf[j * 2][1] = t4[1];
                bf[j * 2 + 1][0] = t4[2]; bf[j * 2 + 1][1] = t4[3];
            }
#pragma unroll
            for (int mi = 0; mi < 4; mi++)
#pragma unroll
                for (int ni = 0; ni < 4; ni++)
                    mma16816h(acc[mi][ni], ah[mi], bf[ni][0], bf[ni][1]);
        }
    }

#pragma unroll
    for (int mi = 0; mi < 4; mi++) {
#pragma unroll
        for (int ni = 0; ni < 4; ni++) {
            int r = m0 + warp_m + mi * 16 + (lane >> 2);
            int cc = n0 + warp_n + ni * 8 + 2 * (lane & 3);
            if (HALF_OUT) {
                __half* C = (__half*)Cc;
                *(__half2*)(C + (size_t)r * Ndim + cc) =
                    __floats2half2_rn(acc[mi][ni][0], acc[mi][ni][1]);
                *(__half2*)(C + (size_t)(r + 8) * Ndim + cc) =
                    __floats2half2_rn(acc[mi][ni][2], acc[mi][ni][3]);
            } else {
                float* C = (float*)Cc;
                *(float2*)(C + (size_t)r * Ndim + cc) = make_float2(acc[mi][ni][0], acc[mi][ni][1]);
                *(float2*)(C + (size_t)(r + 8) * Ndim + cc) = make_float2(acc[mi][ni][2], acc[mi][ni][3]);
            }
        }
    }
}

// ---------------------------------------------------------------------------
// HMMA fp16 flash attention (R15 config + warp-uniform rescale skip):
// BQ=64, 128 thr / 4 warps, double-buffered K/V, heavy-first.
// ---------------------------------------------------------------------------
#define AROW 136
#define ATILE (64 * AROW)
#define ATILEB (ATILE * 2)
#define ASMEM_TOTAL (5 * ATILEB)

__global__ __launch_bounds__(128, 2)
void attn_hmma_kernel(const int* __restrict__ seq_lengths) {
    const uint32_t sbase = smem_to_u32(dynsmem);
    const uint32_t qsb = sbase;

    const int b = blockIdx.z;
    const int h = blockIdx.y;
    const int q0 = (gridDim.x - 1 - blockIdx.x) * 64;
    const int hk = h >> 2;
    const int tid = threadIdx.x;
    const int warp = tid >> 5;
    const int lane = tid & 31;
    const int seqlen = seq_lengths[b];
    const int bT = b * T_;
    const int wq0 = q0 + warp * 16;
    const int r0 = lane >> 2;

    const int kthi = q0 >> 6;
    const int ktlo = (q0 > WINDOW_) ? ((q0 - WINDOW_) >> 6) : 0;
    const int extra = (ktlo > 0) ? 1 : 0;
    const int nt = (kthi - ktlo + 1) + extra;

    auto kt_of = [&](int it) { return extra ? ((it == 0) ? 0 : (ktlo + it - 1)) : it; };

    auto kv_load = [&](int it, int buf) {
        const int kbase = kt_of(it) * 64;
        const uint32_t kb = sbase + (1 + 2 * buf) * ATILEB;
        const uint32_t vb = sbase + (2 + 2 * buf) * ATILEB;
#pragma unroll
        for (int i = 0; i < 8; i++) {
            int id = tid + i * 128;
            int row = id >> 4, c = id & 15;
            size_t rbase = (size_t)(bT + kbase + row) * QKVC_ + hk * 128 + c * 8;
            uint32_t soff = row * 272 + c * 16;
            const void* gk = g_qkv + rbase + C_;
            const void* gv = g_qkv + rbase + C_ + KVC_;
            asm volatile("cp.async.cg.shared.global [%0], [%1], 16;\n" :: "r"(kb + soff), "l"(gk));
            asm volatile("cp.async.cg.shared.global [%0], [%1], 16;\n" :: "r"(vb + soff), "l"(gv));
        }
        asm volatile("cp.async.commit_group;\n" ::: "memory");
    };

#pragma unroll
    for (int i = 0; i < 8; i++) {
        int id = tid + i * 128;
        int row = id >> 4, c = id & 15;
        const void* g = g_qkv + (size_t)(bT + q0 + row) * QKVC_ + h * 128 + c * 8;
        uint32_t d = qsb + row * 272 + c * 16;
        asm volatile("cp.async.cg.shared.global [%0], [%1], 16;\n" :: "r"(d), "l"(g));
    }
    asm volatile("cp.async.commit_group;\n" ::: "memory");
    kv_load(0, 0);
    asm volatile("cp.async.wait_group 1;\n" ::: "memory");
    __syncthreads();

    uint32_t qf[8][4];
    {
        const int lrow = (lane & 7) + ((lane & 8) ? 8 : 0);
        const int lcol = (lane & 16) ? 16 : 0;
#pragma unroll
        for (int ks = 0; ks < 8; ks++)
            ldsm_x4(qf[ks], qsb + (warp * 16 + lrow) * 272 + ks * 32 + lcol);
    }

    float O[16][4];
#pragma unroll
    for (int t = 0; t < 16; t++)
#pragma unroll
        for (int e = 0; e < 4; e++) O[t][e] = 0.0f;
    float m0r = -1e30f, m1r = -1e30f, l0r = 0.0f, l1r = 0.0f;

    const int krowA = (lane & 7) + ((lane & 16) ? 8 : 0);
    const int kcolB = (lane & 8) ? 16 : 0;
    const int vrowA = (lane & 7) + ((lane & 8) ? 8 : 0);
    const int vcolB = (lane & 16) ? 16 : 0;

    for (int it = 0; it < nt; it++) {
        const int buf = it & 1;
        const int kbase = kt_of(it) * 64;

        asm volatile("cp.async.wait_group 0;\n" ::: "memory");
        __syncthreads();
        if (it + 1 < nt) kv_load(it + 1, buf ^ 1);

        const uint32_t ksb = sbase + (1 + 2 * buf) * ATILEB;
        const uint32_t vsb = sbase + (2 + 2 * buf) * ATILEB;

        float S[8][4];
#pragma unroll
        for (int j = 0; j < 8; j++)
#pragma unroll
            for (int e = 0; e < 4; e++) S[j][e] = 0.0f;
#pragma unroll
        for (int ks = 0; ks < 8; ks++) {
#pragma unroll
            for (int np = 0; np < 4; np++) {
                uint32_t kf[4];
                ldsm_x4(kf, ksb + (np * 16 + krowA) * 272 + ks * 32 + kcolB);
                mma16816h(S[2 * np], qf[ks], kf[0], kf[1]);
                mma16816h(S[2 * np + 1], qf[ks], kf[2], kf[3]);
            }
        }

        const bool needmask = !((kbase + 63 <= wq0) && (wq0 + 15 - kbase <= WINDOW_));
        if (needmask) {
#pragma unroll
            for (int j = 0; j < 8; j++) {
                int kk = kbase + j * 8 + 2 * (lane & 3);
#pragma unroll
                for (int e = 0; e < 4; e++) {
                    int q = wq0 + r0 + ((e >= 2) ? 8 : 0);
                    int k = kk + (e & 1);
                    bool ok = (k <= q) && (((q - k) <= WINDOW_) || (k < SINK_));
                    if (!ok) S[j][e] = -1e30f;
                }
            }
        }

        float mx0 = -1e30f, mx1 = -1e30f;
#pragma unroll
        for (int j = 0; j < 8; j++) {
            mx0 = fmaxf(mx0, fmaxf(S[j][0], S[j][1]));
            mx1 = fmaxf(mx1, fmaxf(S[j][2], S[j][3]));
        }
        mx0 = fmaxf(mx0, __shfl_xor_sync(0xffffffffu, mx0, 1));
        mx0 = fmaxf(mx0, __shfl_xor_sync(0xffffffffu, mx0, 2));
        mx1 = fmaxf(mx1, __shfl_xor_sync(0xffffffffu, mx1, 1));
        mx1 = fmaxf(mx1, __shfl_xor_sync(0xffffffffu, mx1, 2));

        float mn0 = fmaxf(m0r, mx0);
        float mn1 = fmaxf(m1r, mx1);
        float a0 = __expf(m0r - mn0);
        float a1 = __expf(m1r - mn1);
        float s0 = 0.0f, s1 = 0.0f;
#pragma unroll
        for (int j = 0; j < 8; j++) {
            S[j][0] = __expf(S[j][0] - mn0);
            S[j][1] = __expf(S[j][1] - mn0);
            S[j][2] = __expf(S[j][2] - mn1);
            S[j][3] = __expf(S[j][3] - mn1);
            s0 += S[j][0] + S[j][1];
            s1 += S[j][2] + S[j][3];
        }
        s0 += __shfl_xor_sync(0xffffffffu, s0, 1);
        s0 += __shfl_xor_sync(0xffffffffu, s0, 2);
        s1 += __shfl_xor_sync(0xffffffffu, s1, 1);
        s1 += __shfl_xor_sync(0xffffffffu, s1, 2);

        l0r = l0r * a0 + s0;
        l1r = l1r * a1 + s1;
        m0r = mn0;
        m1r = mn1;

        // Warp-uniform skip: multiplying O by exactly 1.0 is an identity,
        // so skipping when ALL rows in the warp have alpha==1 is bitwise-safe.
        if (!__all_sync(0xffffffffu, (a0 == 1.0f) && (a1 == 1.0f))) {
#pragma unroll
            for (int t = 0; t < 16; t++) {
                O[t][0] *= a0; O[t][1] *= a0;
                O[t][2] *= a1; O[t][3] *= a1;
            }
        }

#pragma unroll
        for (int ks = 0; ks < 4; ks++) {
            uint32_t pa[4];
            pa[0] = packh2(S[2 * ks][0], S[2 * ks][1]);
            pa[1] = packh2(S[2 * ks][2], S[2 * ks][3]);
            pa[2] = packh2(S[2 * ks + 1][0], S[2 * ks + 1][1]);
            pa[3] = packh2(S[2 * ks + 1][2], S[2 * ks + 1][3]);
#pragma unroll
            for (int nq = 0; nq < 8; nq++) {
                uint32_t vf[4];
                ldsm_x4_t(vf, vsb + (ks * 16 + vrowA) * 272 + nq * 32 + vcolB);
                mma16816h(O[2 * nq], pa, vf[0], vf[1]);
                mma16816h(O[2 * nq + 1], pa, vf[2], vf[3]);
            }
        }
    }

    const int qr0 = wq0 + r0;
    const int qr1 = qr0 + 8;
    float inv0 = (qr0 < seqlen) ? (1.0f / l0r) : 0.0f;
    float inv1 = (qr1 < seqlen) ? (1.0f / l1r) : 0.0f;
#pragma unroll
    for (int t = 0; t < 16; t++) {
        int col = h * 128 + t * 8 + 2 * (lane & 3);
        *(__half2*)(g_yh + (size_t)(bT + qr0) * C_ + col) =
            __floats2half2_rn(O[t][0] * inv0, O[t][1] * inv0);
        *(__half2*)(g_yh + (size_t)(bT + qr1) * C_ + col) =
            __floats2half2_rn(O[t][2] * inv1, O[t][3] * inv1);
    }
}

// ---------------------------------------------------------------------------
// Launch
// ---------------------------------------------------------------------------
extern "C" void kernel_launch(void* const* d_in, const int* in_sizes, int n_in,
                              void* d_out, int out_size) {
    const float* x  = (const float*)d_in[0];
    const float* Wq = (const float*)d_in[1];
    const float* Wk = (const float*)d_in[2];
    const float* Wv = (const float*)d_in[3];
    const float* Wo = (const float*)d_in[4];
    const int* seq_lengths = (const int*)d_in[5];
    float* out = (float*)d_out;

    __half *xh, *qkv, *yh, *wqkv, *wo;
    cudaGetSymbolAddress((void**)&xh, g_xh);
    cudaGetSymbolAddress((void**)&qkv, g_qkv);
    cudaGetSymbolAddress((void**)&yh, g_yh);
    cudaGetSymbolAddress((void**)&wqkv, g_wqkv);
    cudaGetSymbolAddress((void**)&wo, g_wo);

    const int M = B_ * T_;  // 4096

    cudaFuncSetAttribute((const void*)gemm_fp16_kernel<true>,
                         cudaFuncAttributeMaxDynamicSharedMemorySize, GSMEM_TOTAL);
    cudaFuncSetAttribute((const void*)gemm_fp16_kernel<false>,
                         cudaFuncAttributeMaxDynamicSharedMemorySize, GSMEM_TOTAL);
    cudaFuncSetAttribute((const void*)attn_hmma_kernel,
                         cudaFuncAttributeMaxDynamicSharedMemorySize, ASMEM_TOTAL);

    // Single fused prep launch
    prep_kernel<<<(PREP_TOTAL + 255) / 256, 256>>>(x, Wq, Wk, Wv, Wo, xh, wqkv, wo);

    // Fused QKV projection
    gemm_fp16_kernel<true><<<dim3(QKVC_ / 128, M / 128), 256, GSMEM_TOTAL>>>(
        xh, wqkv, qkv, QKVC_, C_);

    // RoPE apply
    {
        int total = M * (H_ + HKV_) * 32;
        rope_apply_kernel<<<(total + 255) / 256, 256>>>(qkv, total);
    }

    // Attention
    attn_hmma_kernel<<<dim3(T_ / 64, H_, B_), 128, ASMEM_TOTAL>>>(seq_lengths);

    // Output projection
    gemm_fp16_kernel<false><<<dim3(C_ / 128, M / 128), 256, GSMEM_TOTAL>>>(
        yh, wo, out, C_, C_);
}